// round 14
// baseline (speedup 1.0000x reference)
#include <cuda_runtime.h>
#include <cuda_fp16.h>
#include <math.h>
#include <cstdint>

#define NN 16384
#define DD 512
#define OO 512
#define BM 128
#define BN 128
#define BK 128                  // k-tile in int8 elements
#define NKT (DD / BK)           // 4 k-tiles
#define ROWB 144                // bytes per smem row (128 + 16 pad) -> conflict-free
#define TXB (BM * ROWB)         // 18432 B, X tile
#define TCB (BN * ROWB)         // 18432 B, C tile
#define STAGE_B (TXB + TCB)     // 36864 B
#define SMEM_BYTES (3 * STAGE_B)  // 110592 B, 3 stages -> 2 CTAs/SM
#define MINN 1e-15f

// Precomputed stats + int8 operands (no allocations -> device globals).
__device__ float g_a0[NN];    // 1 + ||x||^2
__device__ float g_rr[NN];    // 2 / (1 - ||x||^2)
__device__ float g_sx[NN];    // x row quant scale (max|x|/127)
__device__ float g_paq[OO];   // <p,a> / (B * ||a||)   (B = 1-||p||^2 in fp64)
__device__ float g_e2[OO];    // ln(2) * exp(scale)
__device__ float g_sc[OO];    // c row quant scale
__device__ uint4 g_Xq[NN * 32];      // int8 X, 512 B per row
__device__ uint32_t g_Cq[OO * 128];  // int8 C, 512 B per row

__device__ __forceinline__ float warp_sum(float v) {
#pragma unroll
    for (int s = 16; s > 0; s >>= 1) v += __shfl_xor_sync(0xffffffffu, v, s);
    return v;
}
__device__ __forceinline__ float warp_max(float v) {
#pragma unroll
    for (int s = 16; s > 0; s >>= 1)
        v = fmaxf(v, __shfl_xor_sync(0xffffffffu, v, s));
    return v;
}
__device__ __forceinline__ double warp_sum_d(double v) {
#pragma unroll
    for (int s = 16; s > 0; s >>= 1) v += __shfl_xor_sync(0xffffffffu, v, s);
    return v;
}
__device__ __forceinline__ uint32_t pack4(float4 v, float inv) {
    int q0 = __float2int_rn(v.x * inv);
    int q1 = __float2int_rn(v.y * inv);
    int q2 = __float2int_rn(v.z * inv);
    int q3 = __float2int_rn(v.w * inv);
    return (uint32_t)(q0 & 0xff) | ((uint32_t)(q1 & 0xff) << 8) |
           ((uint32_t)(q2 & 0xff) << 16) | ((uint32_t)(q3 & 0xff) << 24);
}

// ---------------- fused prep ----------------
// blocks [0, 1024): X quantize + x-stats, 2 rows per warp.
// blocks [1024, 1536): one block per o: stats (B fp64) + build/quantize c.
__global__ void prep(const float* __restrict__ X, const float* __restrict__ P,
                     const float* __restrict__ A, const float* __restrict__ S) {
    int bid = blockIdx.x;
    int tid = threadIdx.x;
    int wid = tid >> 5, lane = tid & 31;
    if (bid < 1024) {
#pragma unroll
        for (int rr2 = 0; rr2 < 2; rr2++) {
            int row = bid * 16 + wid * 2 + rr2;
            const float4* x4 = reinterpret_cast<const float4*>(X + (size_t)row * DD);
            float4 v[4];
#pragma unroll
            for (int j = 0; j < 4; j++) v[j] = x4[lane * 4 + j];  // contiguous 16 vals
            float s = 0.f, m = 0.f;
#pragma unroll
            for (int j = 0; j < 4; j++) {
                s += v[j].x * v[j].x + v[j].y * v[j].y +
                     v[j].z * v[j].z + v[j].w * v[j].w;
                m = fmaxf(m, fmaxf(fmaxf(fabsf(v[j].x), fabsf(v[j].y)),
                                   fmaxf(fabsf(v[j].z), fabsf(v[j].w))));
            }
            s = warp_sum(s);
            m = warp_max(m);
            m = fmaxf(m, 1e-20f);
            float inv = 127.f / m;
            uint4 q;
            q.x = pack4(v[0], inv);
            q.y = pack4(v[1], inv);
            q.z = pack4(v[2], inv);
            q.w = pack4(v[3], inv);
            g_Xq[row * 32 + lane] = q;
            if (lane == 0) {
                g_a0[row] = 1.f + s;
                g_rr[row] = 2.f / (1.f - s);
                g_sx[row] = m * (1.f / 127.f);
            }
        }
    } else {
        int o = bid - 1024;
        __shared__ double sp2[4];
        __shared__ float spa[4], sa2[4], smx[4];
        __shared__ float sh_paq2, sh_ran, sh_cinv, sh_sc;
        float4 pv, av;
        if (tid < 128) {
            const float4* p4 = reinterpret_cast<const float4*>(P + (size_t)o * DD);
            const float4* a4 = reinterpret_cast<const float4*>(A + (size_t)o * DD);
            pv = p4[tid];
            av = a4[tid];
            double p2 = (double)pv.x * pv.x + (double)pv.y * pv.y +
                        (double)pv.z * pv.z + (double)pv.w * pv.w;
            float pa = pv.x * av.x + pv.y * av.y + pv.z * av.z + pv.w * av.w;
            float a2 = av.x * av.x + av.y * av.y + av.z * av.z + av.w * av.w;
            p2 = warp_sum_d(p2);
            pa = warp_sum(pa);
            a2 = warp_sum(a2);
            if (lane == 0) { sp2[wid] = p2; spa[wid] = pa; sa2[wid] = a2; }
        }
        __syncthreads();
        if (tid == 0) {
            double tp2 = sp2[0] + sp2[1] + sp2[2] + sp2[3];
            double tpa = (double)spa[0] + spa[1] + spa[2] + spa[3];
            double ta2 = (double)sa2[0] + sa2[1] + sa2[2] + sa2[3];
            double B = 1.0 - tp2;    // catastrophic cancellation handled in fp64
            double an = sqrt(ta2);
            if (an < (double)MINN) an = (double)MINN;
            double paq = tpa / (B * an);
            g_paq[o] = (float)paq;
            g_e2[o] = 0.69314718055994530942f * expf(S[o]);
            sh_paq2 = (float)(2.0 * paq);
            sh_ran = (float)(1.0 / an);
        }
        __syncthreads();
        float4 c;
        if (tid < 128) {
            float paq2 = sh_paq2, ran = sh_ran;
            c.x = fmaf(paq2, pv.x, av.x * ran);
            c.y = fmaf(paq2, pv.y, av.y * ran);
            c.z = fmaf(paq2, pv.z, av.z * ran);
            c.w = fmaf(paq2, pv.w, av.w * ran);
            float m = fmaxf(fmaxf(fabsf(c.x), fabsf(c.y)),
                            fmaxf(fabsf(c.z), fabsf(c.w)));
            m = warp_max(m);
            if (lane == 0) smx[wid] = m;
        }
        __syncthreads();
        if (tid == 0) {
            float m = fmaxf(fmaxf(smx[0], smx[1]), fmaxf(smx[2], smx[3]));
            m = fmaxf(m, 1e-20f);
            sh_cinv = 127.f / m;
            sh_sc = m * (1.f / 127.f);
        }
        __syncthreads();
        if (tid < 128) {
            g_Cq[o * 128 + tid] = pack4(c, sh_cinv);
            if (tid == 0) g_sc[o] = sh_sc;
        }
    }
}

// ---------------- PTX helpers ----------------
// int8 MMA m16n8k32: 4096 MACs per instruction, exact s32 accumulation.
#define MMA_S8(d, a, b0, b1)                                                   \
    asm volatile(                                                              \
        "mma.sync.aligned.m16n8k32.row.col.s32.s8.s8.s32 "                     \
        "{%0,%1,%2,%3}, {%4,%5,%6,%7}, {%8,%9}, {%0,%1,%2,%3};"                \
        : "+r"((d)[0]), "+r"((d)[1]), "+r"((d)[2]), "+r"((d)[3])               \
        : "r"((a)[0]), "r"((a)[1]), "r"((a)[2]), "r"((a)[3]), "r"(b0), "r"(b1))

#define LDMX4(r, addr)                                                         \
    asm volatile("ldmatrix.sync.aligned.m8n8.x4.shared.b16 {%0,%1,%2,%3}, [%4];" \
                 : "=r"((r)[0]), "=r"((r)[1]), "=r"((r)[2]), "=r"((r)[3])      \
                 : "r"(addr))

#define CPA16(saddr, gptr)                                                     \
    asm volatile("cp.async.cg.shared.global [%0], [%1], 16;"                   \
                 :: "r"(saddr), "l"(gptr))
#define CPA_COMMIT() asm volatile("cp.async.commit_group;" ::: "memory")
#define CPA_WAIT1() asm volatile("cp.async.wait_group 1;" ::: "memory")

// asinh(arg)*e^s: asinh t = ln(t+sqrt(t^2+1)) = lg2(.)*ln2.
// Fast path (warp-uniform): all lanes |t| >= 64 -> asinh(t) ~= ln(2t).
__device__ __forceinline__ float epi(float xc, float a0, float rr,
                                     float paq, float e2) {
    float arg = (xc - a0 * paq) * rr;
    float tt = fabsf(arg);
    float u;
    if (__any_sync(0xffffffffu, tt < 64.f)) {
        float s;
        asm("sqrt.approx.f32 %0, %1;" : "=f"(s) : "f"(fmaf(tt, tt, 1.f)));
        u = tt + s;
    } else {
        u = tt + tt;
    }
    float r;
    asm("lg2.approx.f32 %0, %1;" : "=f"(r) : "f"(u));
    return copysignf(r * e2, arg);
}

// ---------------- main: SINGLE int8 GEMM (qx @ qc^T) + tiny epilogue ---------
// 128x128 block tile, 256 threads, warp grid 2(M) x 4(N), warp tile 64x32.
__global__ void __launch_bounds__(256, 2) mobius_main(float* __restrict__ out) {
    extern __shared__ char smc[];
    int tid = threadIdx.x;
    int lane = tid & 31, wid = tid >> 5;
    int wm = wid & 1, wn = wid >> 1;
    int m0 = blockIdx.y * BM, n0 = blockIdx.x * BN;

    const char* Xg = reinterpret_cast<const char*>(g_Xq) + (size_t)m0 * 512;
    const char* Cg = reinterpret_cast<const char*>(g_Cq) + (size_t)n0 * 512;
    uint32_t sbase = (uint32_t)__cvta_generic_to_shared(smc);

// per k-tile: 128 rows x 8 chunks of 16B per matrix = 1024 chunks each
#define LOAD_STAGE(stg, kt)                                                    \
    {                                                                          \
        uint32_t st = sbase + (uint32_t)(stg) * STAGE_B;                       \
        int k0 = (kt) * BK;                                                    \
        _Pragma("unroll") for (int j = 0; j < 4; j++) {                        \
            int f = tid + 256 * j;                                             \
            int row = f >> 3, ck = f & 7;                                      \
            uint32_t so = (uint32_t)(row * ROWB + ck * 16);                    \
            size_t go = (size_t)row * 512 + k0 + ck * 16;                      \
            CPA16(st + so, Xg + go);                                           \
            CPA16(st + TXB + so, Cg + go);                                     \
        }                                                                      \
    }

    int acc[4][4][4];
#pragma unroll
    for (int mt = 0; mt < 4; mt++)
#pragma unroll
        for (int nt = 0; nt < 4; nt++)
#pragma unroll
            for (int e = 0; e < 4; e++) acc[mt][nt][e] = 0;

    LOAD_STAGE(0, 0); CPA_COMMIT();
    LOAD_STAGE(1, 1); CPA_COMMIT();

    // ldmatrix per-lane base addresses (bytes, within a stage)
    uint32_t a_base = (uint32_t)((wm * 64 + (lane & 15)) * ROWB + ((lane >> 4) << 4));
    uint32_t b_row = (uint32_t)(wn * 32 + (((lane >> 4) & 1) << 3) + (lane & 7));
    uint32_t b_base = (uint32_t)(b_row * ROWB + (((lane >> 3) & 1) << 4));

    for (int c = 0; c < NKT; ++c) {
        CPA_WAIT1();
        __syncthreads();
        if (c + 2 < NKT) { LOAD_STAGE((c + 2) % 3, c + 2); }
        CPA_COMMIT();

        uint32_t st = sbase + (uint32_t)(c % 3) * STAGE_B;
        uint32_t aA = st + a_base;
        uint32_t aC = st + TXB + b_base;
#pragma unroll
        for (int ks = 0; ks < 4; ks++) {    // 4 x k32 per k-tile of 128
            uint32_t af[4][4], bc[2][4];
#pragma unroll
            for (int mt = 0; mt < 4; mt++)
                LDMX4(af[mt], aA + (uint32_t)(mt * 16 * ROWB + ks * 32));
            LDMX4(bc[0], aC + (uint32_t)(ks * 32));
            LDMX4(bc[1], aC + (uint32_t)(16 * ROWB + ks * 32));
#pragma unroll
            for (int nt = 0; nt < 4; nt++) {
                uint32_t b0 = bc[nt >> 1][2 * (nt & 1)];
                uint32_t b1 = bc[nt >> 1][2 * (nt & 1) + 1];
#pragma unroll
                for (int mt = 0; mt < 4; mt++)
                    MMA_S8(acc[mt][nt], (int*)af[mt], b0, b1);
            }
        }
    }

    // ---- epilogue: xc = idot*sx*sc; arg = (xc - a0*paq)*rr ----
    int g = lane >> 2, t = lane & 3;
    float a0r[4][2], rrr[4][2], sxr[4][2];
#pragma unroll
    for (int mt = 0; mt < 4; mt++)
#pragma unroll
        for (int h = 0; h < 2; h++) {
            int r = m0 + wm * 64 + mt * 16 + g + h * 8;
            a0r[mt][h] = g_a0[r];
            rrr[mt][h] = g_rr[r];
            sxr[mt][h] = g_sx[r];
        }
    float paqc[4][2], e2c[4][2], scc[4][2];
#pragma unroll
    for (int nt = 0; nt < 4; nt++)
#pragma unroll
        for (int w = 0; w < 2; w++) {
            int cc = n0 + wn * 32 + nt * 8 + 2 * t + w;
            paqc[nt][w] = g_paq[cc];
            e2c[nt][w] = g_e2[cc];
            scc[nt][w] = g_sc[cc];
        }
#pragma unroll
    for (int mt = 0; mt < 4; mt++) {
#pragma unroll
        for (int h = 0; h < 2; h++) {
            int r = m0 + wm * 64 + mt * 16 + g + h * 8;
            float* orow = out + (size_t)r * OO + n0 + wn * 32 + 2 * t;
#pragma unroll
            for (int nt = 0; nt < 4; nt++) {
                float s0 = sxr[mt][h] * scc[nt][0];
                float s1 = sxr[mt][h] * scc[nt][1];
                float o0 = epi((float)acc[mt][nt][h * 2 + 0] * s0,
                               a0r[mt][h], rrr[mt][h], paqc[nt][0], e2c[nt][0]);
                float o1 = epi((float)acc[mt][nt][h * 2 + 1] * s1,
                               a0r[mt][h], rrr[mt][h], paqc[nt][1], e2c[nt][1]);
                *reinterpret_cast<float2*>(orow + nt * 8) = make_float2(o0, o1);
            }
        }
    }
}

extern "C" void kernel_launch(void* const* d_in, const int* in_sizes, int n_in,
                              void* d_out, int out_size) {
    const float* x = (const float*)d_in[0];      // [N, D]
    const float* p = (const float*)d_in[1];      // [O, D]
    const float* a = (const float*)d_in[2];      // [O, D]
    const float* s = (const float*)d_in[3];      // [O]
    float* out = (float*)d_out;                  // [N, O]

    prep<<<1024 + OO, 256>>>(x, p, a, s);
    cudaFuncSetAttribute(mobius_main, cudaFuncAttributeMaxDynamicSharedMemorySize,
                         SMEM_BYTES);
    dim3 grid(OO / BN, NN / BM);
    mobius_main<<<grid, 256, SMEM_BYTES>>>(out);
}